// round 13
// baseline (speedup 1.0000x reference)
#include <cuda_runtime.h>
#include <math.h>
#include <stdint.h>

#define ENC 1024
#define PRED 320
#define JH 512
#define VOCAB 29
#define BLANK 28
#define MAXSYM 6
#define BATCH 32
#define TLEN 48
#define NSTEPS 288
#define ZDIM 1344
#define CSIZE 8
#define MB 2
#define NTHREADS 640
#define UNITS_PER (PRED / CSIZE)   // 40
#define GROWS (4 * UNITS_PER)      // 160 local gate rows
#define JROWS_PER (JH / CSIZE)     // 64

// Transposed weight scratch (one-time fill per launch; ~9.3 MB)
__device__ float d_WiT0[PRED * 4 * PRED];   // [320 cols][1280 rows]
__device__ float d_WhT0[PRED * 4 * PRED];
__device__ float d_WiT1[PRED * 4 * PRED];
__device__ float d_WhT1[PRED * 4 * PRED];
__device__ float d_Wj1T[ZDIM * JH];         // [1344 cols][512 rows]

#define CLUSTER_SYNC() do { \
    asm volatile("barrier.cluster.arrive.aligned;" ::: "memory"); \
    asm volatile("barrier.cluster.wait.aligned;"   ::: "memory"); \
} while (0)

__device__ __forceinline__ float sigf(float v) { return 1.0f / (1.0f + expf(-v)); }

__device__ __forceinline__ float wredsum(float v) {
    #pragma unroll
    for (int o = 16; o > 0; o >>= 1) v += __shfl_down_sync(0xffffffffu, v, o);
    return v;
}

__device__ __forceinline__ uint32_t s2u(const void* p) {
    return (uint32_t)__cvta_generic_to_shared((void*)p);
}

__device__ __forceinline__ void st_peer(uint32_t addr, int rank, float v) {
    uint32_t pa;
    asm volatile("mapa.shared::cluster.u32 %0, %1, %2;" : "=r"(pa) : "r"(addr), "r"(rank));
    asm volatile("st.shared::cluster.f32 [%0], %1;" :: "r"(pa), "f"(v));
}

// ---------------- tiled transpose: out[c][r] = in[r][c]; R,C multiples of 32 ----------------
__global__ void transpose_kernel(const float* __restrict__ in, int R, int C, int which) {
    float* out = (which == 0) ? d_WiT0 : (which == 1) ? d_WhT0 :
                 (which == 2) ? d_WiT1 : (which == 3) ? d_WhT1 : d_Wj1T;
    __shared__ float tile[32][33];
    int tilesC = C >> 5, tilesR = R >> 5;
    int ntiles = tilesC * tilesR;
    for (int t = blockIdx.x; t < ntiles; t += gridDim.x) {
        int tc = t % tilesC, tr = t / tilesC;
        int c0 = tc << 5, r0 = tr << 5;
        __syncthreads();
        #pragma unroll
        for (int j = 0; j < 32; j += 8)
            tile[threadIdx.y + j][threadIdx.x] = in[(size_t)(r0 + threadIdx.y + j) * C + c0 + threadIdx.x];
        __syncthreads();
        #pragma unroll
        for (int j = 0; j < 32; j += 8)
            out[(size_t)(c0 + threadIdx.y + j) * R + r0 + threadIdx.x] = tile[threadIdx.x][threadIdx.y + j];
    }
}

// ---------------- dynamic shared-memory layout ----------------
struct Smem {
    float L0in[MB][2 * PRED];     // [0:320]=e, [320:640]=h0(state, full)
    float L1in[MB][2 * PRED];     // [0:320]=h0p(full), [320:640]=h1(state, full)
    float zj[MB][ZDIM];           // [0:1024]=f, [1024:1344]=h1p(full)
    float c0s[MB][UNITS_PER], c1s[MB][UNITS_PER];   // rank-local c state
    float c0p[MB][UNITS_PER], c1p[MB][UNITS_PER];
    float g[MB][GROWS];           // local gate pre-activations
    float scratch[5120];          // gates: 16*2*160 = 5120; joint: 32*2*64 = 4096 subset
    float hid[MB][JH];
    float logit[MB][32];
    int   lt[MB][NSTEPS];
};
#define SMEM_BYTES ((int)sizeof(Smem))

// ---------------- gate GEMV: 16 col-splits x 40 cols, float4 rows, 640 threads ----------------
// Local rows: 160 (4 gates x 40 units for this rank). Cols: 640 = [in0(320) | hid(320)].
// split = tid/40 (0..15): splits 0-7 read WiT (cb=split*40), 8-15 read WhT (cb=(split-8)*40).
// rg = tid%40 -> local rows 4rg..4rg+3 (one float4 weight load per column).
__device__ __forceinline__ void gemv_gates_T(
    const float* __restrict__ WiT, const float* __restrict__ WhT,
    const float* __restrict__ bias,
    const float (*in)[2 * PRED],       // [MB][640]
    float (*gout)[GROWS],              // [MB][160]
    float* scratch, int rank, int tid)
{
    {
        int split = tid / 40;          // 0..15
        int rg    = tid - split * 40;  // 0..39
        int rowb  = 4 * rg;            // local row base 0..156
        int g     = rg / 10;           // gate index (= rowb/40; 4-row groups don't cross gates)
        const float* WT = (split < 8) ? WiT : WhT;
        int cb = (split & 7) * 40;     // col base within the 320-wide matrix
        // global weight row = g*320 + rank*40 + (rowb - 40g) = 280g + 40*rank + rowb
        const float* w0 = WT + (cb * 1280) + 280 * g + 40 * rank + rowb;
        const float* a0 = &in[0][(split < 8 ? 0 : 320) + cb];
        const float* a1 = &in[1][(split < 8 ? 0 : 320) + cb];
        float acc[4][2] = {{0.f,0.f},{0.f,0.f},{0.f,0.f},{0.f,0.f}};
        #pragma unroll 4
        for (int cc = 0; cc < 40; ++cc) {
            float4 w = *(const float4*)(w0 + cc * 1280);
            float x0 = a0[cc], x1 = a1[cc];
            acc[0][0] = fmaf(w.x, x0, acc[0][0]); acc[0][1] = fmaf(w.x, x1, acc[0][1]);
            acc[1][0] = fmaf(w.y, x0, acc[1][0]); acc[1][1] = fmaf(w.y, x1, acc[1][1]);
            acc[2][0] = fmaf(w.z, x0, acc[2][0]); acc[2][1] = fmaf(w.z, x1, acc[2][1]);
            acc[3][0] = fmaf(w.w, x0, acc[3][0]); acc[3][1] = fmaf(w.w, x1, acc[3][1]);
        }
        #pragma unroll
        for (int i = 0; i < 4; ++i) {
            int lrow = rowb + i;
            scratch[(split * 2 + 0) * GROWS + lrow] = acc[i][0];
            scratch[(split * 2 + 1) * GROWS + lrow] = acc[i][1];
        }
    }
    __syncthreads();
    if (tid < MB * GROWS) {            // 320 outputs
        int m = tid / GROWS, r = tid - m * GROWS;
        float v = scratch[(0 * 2 + m) * GROWS + r];
        #pragma unroll
        for (int s = 1; s < 16; ++s) v += scratch[(s * 2 + m) * GROWS + r];
        int g = r / UNITS_PER, lu = r - g * UNITS_PER;
        gout[m][r] = v + bias[g * PRED + rank * UNITS_PER + lu];
    }
    // caller syncs before consuming gout
}

// ---------------- joint GEMV: 32 col-splits x 42 cols, float4 rows, 512 threads ----------------
// Local rows: 64 (rank slice of 512). Cols: 1344 = 32 splits x 42.
// split = tid>>4 (0..31), rg = tid&15 -> rows 4rg..4rg+3 (float4).
__device__ __forceinline__ void gemv_joint_T(
    const float* __restrict__ WT, const float* __restrict__ bias,
    const float (*zin)[ZDIM],          // [MB][1344]
    float (*hid)[JH],                  // [MB][512], assembled cluster-wide
    float* scratch, int rank, int tid)
{
    if (tid < 512) {
        int split = tid >> 4;          // 0..31
        int rg    = tid & 15;
        int rowb  = 4 * rg;            // 0..60
        const float* w0 = WT + (split * 42) * 512 + rank * JROWS_PER + rowb;
        const float* a0 = &zin[0][split * 42];
        const float* a1 = &zin[1][split * 42];
        float acc[4][2] = {{0.f,0.f},{0.f,0.f},{0.f,0.f},{0.f,0.f}};
        #pragma unroll 6
        for (int cc = 0; cc < 42; ++cc) {
            float4 w = *(const float4*)(w0 + cc * 512);
            float x0 = a0[cc], x1 = a1[cc];
            acc[0][0] = fmaf(w.x, x0, acc[0][0]); acc[0][1] = fmaf(w.x, x1, acc[0][1]);
            acc[1][0] = fmaf(w.y, x0, acc[1][0]); acc[1][1] = fmaf(w.y, x1, acc[1][1]);
            acc[2][0] = fmaf(w.z, x0, acc[2][0]); acc[2][1] = fmaf(w.z, x1, acc[2][1]);
            acc[3][0] = fmaf(w.w, x0, acc[3][0]); acc[3][1] = fmaf(w.w, x1, acc[3][1]);
        }
        #pragma unroll
        for (int i = 0; i < 4; ++i) {
            int lrow = rowb + i;
            scratch[(split * 2 + 0) * JROWS_PER + lrow] = acc[i][0];
            scratch[(split * 2 + 1) * JROWS_PER + lrow] = acc[i][1];
        }
    }
    __syncthreads();
    if (tid < MB * JROWS_PER) {        // 128 outputs
        int m = tid / JROWS_PER, lr = tid - m * JROWS_PER;
        float v = scratch[(0 * 2 + m) * JROWS_PER + lr];
        #pragma unroll
        for (int s = 1; s < 32; ++s) v += scratch[(s * 2 + m) * JROWS_PER + lr];
        v += bias[rank * JROWS_PER + lr];
        v = v > 0.f ? v : 0.f;
        uint32_t ad = s2u(&hid[m][rank * JROWS_PER + lr]);
        #pragma unroll
        for (int rk = 0; rk < CSIZE; ++rk) st_peer(ad, rk, v);
    }
    // caller cluster-syncs
}

__global__ __launch_bounds__(NTHREADS, 1) __cluster_dims__(CSIZE, 1, 1)
void rnnt_greedy_kernel(const float* __restrict__ x,
                        const int*   __restrict__ out_lens,
                        const float* __restrict__ emb,
                        const float* __restrict__ b0, const float* __restrict__ b1,
                        const float* __restrict__ bj1,
                        const float* __restrict__ Wj2, const float* __restrict__ bj2,
                        float* __restrict__ d_out, int write_lc)
{
    extern __shared__ __align__(16) char smem_raw[];
    Smem& S = *reinterpret_cast<Smem*>(smem_raw);

    const int tid  = threadIdx.x;
    const int lane = tid & 31;
    const int warp = tid >> 5;

    uint32_t rank;
    asm("mov.u32 %0, %%cluster_ctarank;" : "=r"(rank));
    const int cid   = blockIdx.x / CSIZE;
    const int bbase = cid * MB;

    __shared__ int s_last[MB], s_lc[MB], s_ti[MB], s_sa[MB], s_nb[MB], s_olen[MB];
    __shared__ int s_alldone;

    // ---- init ----
    for (int i = tid; i < MB * PRED; i += NTHREADS) {
        int m = i / PRED, j = i - m * PRED;
        S.L0in[m][PRED + j] = 0.f;   // h0 = 0
        S.L1in[m][PRED + j] = 0.f;   // h1 = 0
    }
    for (int i = tid; i < MB * UNITS_PER; i += NTHREADS) {
        int m = i / UNITS_PER, j = i - m * UNITS_PER;
        S.c0s[m][j] = 0.f; S.c1s[m][j] = 0.f;
    }
    for (int i = tid; i < MB * NSTEPS; i += NTHREADS) {
        int m = i / NSTEPS, j = i - m * NSTEPS;
        S.lt[m][j] = -1;
    }
    if (tid == 0) {
        #pragma unroll
        for (int m = 0; m < MB; ++m) {
            s_last[m] = -1; s_lc[m] = 0; s_ti[m] = 0; s_sa[m] = 0; s_nb[m] = 0;
            s_olen[m] = out_lens[bbase + m];
        }
        s_alldone = 0;
    }
    __syncthreads();
    CLUSTER_SYNC();

    for (int step = 0; step < NSTEPS; ++step) {
        const bool active = (s_alldone == 0);   // uniform across cluster

        // ---- P0: encoder frame -> zj[.][0:1024], embedding -> L0in[.][0:320] ----
        if (active) {
            for (int i = tid; i < MB * ENC; i += NTHREADS) {
                int m = i >> 10, col = i & (ENC - 1);
                int fi = s_ti[m]; if (fi > TLEN - 1) fi = TLEN - 1;
                S.zj[m][col] = x[((bbase + m) * TLEN + fi) * ENC + col];
            }
            for (int i = tid; i < MB * PRED; i += NTHREADS) {
                int m = i / PRED, col = i - m * PRED;
                int lab = s_last[m];
                int labc = lab > (VOCAB - 2) ? (VOCAB - 2) : lab;
                S.L0in[m][col] = (lab >= 0) ? emb[labc * PRED + col] : 0.0f;
            }
        }
        __syncthreads();

        // ---- P1: layer-0 gates (transposed GEMV; internal sync) ----
        if (active)
            gemv_gates_T(d_WiT0, d_WhT0, b0, S.L0in, S.g, S.scratch, (int)rank, tid);
        __syncthreads();

        // ---- P2: LSTM0 nonlinearity; broadcast h0p slice to all 8 CTAs ----
        if (active && tid < MB * UNITS_PER) {
            int m = tid / UNITS_PER, lu = tid - m * UNITS_PER;
            float gi = S.g[m][lu],                 gf = S.g[m][UNITS_PER + lu];
            float gg = S.g[m][2 * UNITS_PER + lu], go = S.g[m][3 * UNITS_PER + lu];
            float c  = sigf(gf) * S.c0s[m][lu] + sigf(gi) * tanhf(gg);
            S.c0p[m][lu] = c;
            float h  = sigf(go) * tanhf(c);
            uint32_t a = s2u(&S.L1in[m][rank * UNITS_PER + lu]);
            #pragma unroll
            for (int rk = 0; rk < CSIZE; ++rk) st_peer(a, rk, h);
        }
        CLUSTER_SYNC();   // S1: full h0p in L1in[.][0:320] everywhere

        // ---- P3: layer-1 gates ----
        if (active)
            gemv_gates_T(d_WiT1, d_WhT1, b1, S.L1in, S.g, S.scratch, (int)rank, tid);
        __syncthreads();

        // ---- P4: LSTM1 nonlinearity; broadcast h1p slice ----
        if (active && tid < MB * UNITS_PER) {
            int m = tid / UNITS_PER, lu = tid - m * UNITS_PER;
            float gi = S.g[m][lu],                 gf = S.g[m][UNITS_PER + lu];
            float gg = S.g[m][2 * UNITS_PER + lu], go = S.g[m][3 * UNITS_PER + lu];
            float c  = sigf(gf) * S.c1s[m][lu] + sigf(gi) * tanhf(gg);
            S.c1p[m][lu] = c;
            float h  = sigf(go) * tanhf(c);
            uint32_t a = s2u(&S.zj[m][ENC + rank * UNITS_PER + lu]);
            #pragma unroll
            for (int rk = 0; rk < CSIZE; ++rk) st_peer(a, rk, h);
        }
        CLUSTER_SYNC();   // S2: full [f|h1p] in zj everywhere

        // ---- P5: joint hidden (transposed GEMV; internal sync; broadcasts hid) ----
        if (active)
            gemv_joint_T(d_Wj1T, bj1, S.zj, S.hid, S.scratch, (int)rank, tid);
        CLUSTER_SYNC();   // S3: full hid everywhere

        // ---- P6: logits (replicated; warp per vocab row) ----
        if (active) {
            for (int v = warp; v < VOCAB; v += (NTHREADS / 32)) {
                const float* w = Wj2 + v * JH + 16 * lane;
                float4 wv[4];
                #pragma unroll
                for (int j = 0; j < 4; ++j) wv[j] = *(const float4*)(w + 4 * j);
                float acc0 = 0.f, acc1 = 0.f;
                #pragma unroll
                for (int j = 0; j < 4; ++j) {
                    float4 h0v = *(const float4*)&S.hid[0][16 * lane + 4 * j];
                    float4 h1v = *(const float4*)&S.hid[1][16 * lane + 4 * j];
                    acc0 = fmaf(wv[j].x, h0v.x, acc0); acc0 = fmaf(wv[j].y, h0v.y, acc0);
                    acc0 = fmaf(wv[j].z, h0v.z, acc0); acc0 = fmaf(wv[j].w, h0v.w, acc0);
                    acc1 = fmaf(wv[j].x, h1v.x, acc1); acc1 = fmaf(wv[j].y, h1v.y, acc1);
                    acc1 = fmaf(wv[j].z, h1v.z, acc1); acc1 = fmaf(wv[j].w, h1v.w, acc1);
                }
                acc0 = wredsum(acc0);
                acc1 = wredsum(acc1);
                if (lane == 0) {
                    float bb = bj2[v];
                    S.logit[0][v] = acc0 + bb;
                    S.logit[1][v] = acc1 + bb;
                }
            }
        }
        __syncthreads();

        // ---- P7: argmax + control (replicated; identical in every CTA) ----
        if (active && tid == 0) {
            int ndone = 0;
            #pragma unroll
            for (int m = 0; m < MB; ++m) {
                float best = S.logit[m][0]; int k = 0;
                #pragma unroll
                for (int v = 1; v < VOCAB; ++v) {
                    float lv = S.logit[m][v];
                    if (lv > best) { best = lv; k = v; }
                }
                int ti = s_ti[m], sa = s_sa[m], lc = s_lc[m];
                bool blk = (k == BLANK);
                if (blk) ti += 1;
                bool done = (ti >= s_olen[m]);
                if (blk) sa = 0;
                bool nb = !(done || blk);
                if (nb) {
                    lc += 1;
                    if (lc <= NSTEPS - 1) S.lt[m][lc] += (k + 1);  // JAX scatter: OOB dropped
                    sa += 1;
                }
                {
                    int pos = lc; if (pos > NSTEPS - 1) pos = NSTEPS - 1;
                    s_last[m] = S.lt[m][pos];                       // JAX gather: clamp
                }
                if (sa >= MAXSYM) { ti += 1; sa = 0; }
                s_ti[m] = ti; s_sa[m] = sa; s_lc[m] = lc; s_nb[m] = nb ? 1 : 0;
                if (ti >= s_olen[m]) ndone += 1;
            }
            if (ndone == MB) s_alldone = 1;   // outputs frozen from here on
        }
        __syncthreads();

        // ---- P8: conditional state commit ----
        if (active) {
            for (int i = tid; i < MB * PRED; i += NTHREADS) {
                int m = i / PRED, u = i - m * PRED;
                if (s_nb[m]) {
                    S.L0in[m][PRED + u] = S.L1in[m][u];        // h0 <- h0p
                    S.L1in[m][PRED + u] = S.zj[m][ENC + u];    // h1 <- h1p
                }
            }
            if (tid < MB * UNITS_PER) {
                int m = tid / UNITS_PER, lu = tid - m * UNITS_PER;
                if (s_nb[m]) { S.c0s[m][lu] = S.c0p[m][lu]; S.c1s[m][lu] = S.c1p[m][lu]; }
            }
        }
        CLUSTER_SYNC();   // S4: protects h0p/h1p regions against next step's peer writes
    }

    // ---- output (rank 0): lt as float32, then lc ----
    if (rank == 0) {
        for (int m = 0; m < MB; ++m) {
            for (int i = tid; i < NSTEPS; i += NTHREADS)
                d_out[(bbase + m) * NSTEPS + i] = (float)S.lt[m][i];
        }
        if (tid == 0 && write_lc) {
            d_out[BATCH * NSTEPS + bbase + 0] = (float)s_lc[0];
            d_out[BATCH * NSTEPS + bbase + 1] = (float)s_lc[1];
        }
    }
}

extern "C" void kernel_launch(void* const* d_in, const int* in_sizes, int n_in,
                              void* d_out, int out_size) {
    const float* x        = (const float*)d_in[0];
    const int*   out_lens = (const int*)  d_in[1];
    const float* emb      = (const float*)d_in[2];
    const float* Wi0      = (const float*)d_in[3];
    const float* Wh0      = (const float*)d_in[4];
    const float* b0       = (const float*)d_in[5];
    const float* Wi1      = (const float*)d_in[6];
    const float* Wh1      = (const float*)d_in[7];
    const float* b1       = (const float*)d_in[8];
    const float* Wj1      = (const float*)d_in[9];
    const float* bj1      = (const float*)d_in[10];
    const float* Wj2      = (const float*)d_in[11];
    const float* bj2      = (const float*)d_in[12];

    int write_lc = (out_size >= BATCH * NSTEPS + BATCH) ? 1 : 0;

    // Opt-in to >48KB dynamic smem (idempotent; not a memory allocation).
    static int attr_done = 0;
    if (!attr_done) {
        cudaFuncSetAttribute(rnnt_greedy_kernel,
                             cudaFuncAttributeMaxDynamicSharedMemorySize, SMEM_BYTES);
        attr_done = 1;
    }

    dim3 tb(32, 8);
    transpose_kernel<<<512, tb>>>(Wi0, 4 * PRED, PRED, 0);
    transpose_kernel<<<512, tb>>>(Wh0, 4 * PRED, PRED, 1);
    transpose_kernel<<<512, tb>>>(Wi1, 4 * PRED, PRED, 2);
    transpose_kernel<<<512, tb>>>(Wh1, 4 * PRED, PRED, 3);
    transpose_kernel<<<512, tb>>>(Wj1, JH, ZDIM, 4);

    rnnt_greedy_kernel<<<(BATCH / MB) * CSIZE, NTHREADS, SMEM_BYTES>>>(
        x, out_lens, emb, b0, b1, bj1, Wj2, bj2,
        (float*)d_out, write_lc);
}

// round 15
// speedup vs baseline: 1.1526x; 1.1526x over previous
#include <cuda_runtime.h>
#include <math.h>
#include <stdint.h>

#define ENC 1024
#define PRED 320
#define JH 512
#define VOCAB 29
#define BLANK 28
#define MAXSYM 6
#define BATCH 32
#define TLEN 48
#define NSTEPS 288
#define ZDIM 1344
#define CSIZE 8
#define MB 4
#define NTHREADS 640
#define UNITS_PER (PRED / CSIZE)   // 40
#define GROWS (4 * UNITS_PER)      // 160 local gate rows
#define JROWS_PER (JH / CSIZE)     // 64

// Transposed weight scratch (one-time fill per launch; ~9.3 MB)
__device__ float d_WiT0[PRED * 4 * PRED];   // [320 cols][1280 rows]
__device__ float d_WhT0[PRED * 4 * PRED];
__device__ float d_WiT1[PRED * 4 * PRED];
__device__ float d_WhT1[PRED * 4 * PRED];
__device__ float d_Wj1T[ZDIM * JH];         // [1344 cols][512 rows]

#define CLUSTER_SYNC() do { \
    asm volatile("barrier.cluster.arrive.aligned;" ::: "memory"); \
    asm volatile("barrier.cluster.wait.aligned;"   ::: "memory"); \
} while (0)

__device__ __forceinline__ float sigf(float v) { return 1.0f / (1.0f + expf(-v)); }

__device__ __forceinline__ uint32_t s2u(const void* p) {
    return (uint32_t)__cvta_generic_to_shared((void*)p);
}

__device__ __forceinline__ void st_peer(uint32_t addr, int rank, float v) {
    uint32_t pa;
    asm volatile("mapa.shared::cluster.u32 %0, %1, %2;" : "=r"(pa) : "r"(addr), "r"(rank));
    asm volatile("st.shared::cluster.f32 [%0], %1;" :: "r"(pa), "f"(v));
}

// ---------------- tiled transpose: out[c][r] = in[r][c]; R,C multiples of 32 ----------------
__global__ void transpose_kernel(const float* __restrict__ in, int R, int C, int which) {
    float* out = (which == 0) ? d_WiT0 : (which == 1) ? d_WhT0 :
                 (which == 2) ? d_WiT1 : (which == 3) ? d_WhT1 : d_Wj1T;
    __shared__ float tile[32][33];
    int tilesC = C >> 5, tilesR = R >> 5;
    int ntiles = tilesC * tilesR;
    for (int t = blockIdx.x; t < ntiles; t += gridDim.x) {
        int tc = t % tilesC, tr = t / tilesC;
        int c0 = tc << 5, r0 = tr << 5;
        __syncthreads();
        #pragma unroll
        for (int j = 0; j < 32; j += 8)
            tile[threadIdx.y + j][threadIdx.x] = in[(size_t)(r0 + threadIdx.y + j) * C + c0 + threadIdx.x];
        __syncthreads();
        #pragma unroll
        for (int j = 0; j < 32; j += 8)
            out[(size_t)(c0 + threadIdx.y + j) * R + r0 + threadIdx.x] = tile[threadIdx.x][threadIdx.y + j];
    }
}

// ---------------- dynamic shared-memory layout ----------------
// Activations interleaved [col][MB] so one LDS.128 fetches all 4 batch values (warp-broadcast).
struct Smem {
    float L0in[2 * PRED][MB];     // cols [0:320]=e, [320:640]=h0(state)
    float L1in[2 * PRED][MB];     // cols [0:320]=h0p, [320:640]=h1(state)
    float zj[ZDIM][MB];           // cols [0:1024]=f, [1024:1344]=h1p
    float c0s[MB][UNITS_PER], c1s[MB][UNITS_PER];
    float c0p[MB][UNITS_PER], c1p[MB][UNITS_PER];
    float g[MB][GROWS];
    float scratch[16 * MB * GROWS];   // gates: 16*4*160 = 10240; joint uses 32*4*64 = 8192 subset
    float hid[MB][JH];
    float logit[MB][32];
    int   lt[MB][NSTEPS];
};
#define SMEM_BYTES ((int)sizeof(Smem))

// ---------------- gate GEMV: 16 col-splits x 40 cols, float4 rows x 4 batches ----------------
// Local rows: 160 (4 gates x 40 units for this rank). Cols: 640 = [in0(320) | hid(320)].
// split = tid/40 (0..15): splits 0-7 read WiT (cb=split*40), 8-15 read WhT.
// rg = tid%40 -> local rows 4rg..4rg+3. Inner: 1 LDG.128 + 1 LDS.128(broadcast) + 16 FMA.
__device__ __forceinline__ void gemv_gates_T(
    const float* __restrict__ WiT, const float* __restrict__ WhT,
    const float* __restrict__ bias,
    const float (*in)[MB],             // [640][MB]
    float (*gout)[GROWS],              // [MB][160]
    float* scratch, int rank, int tid)
{
    {
        int split = tid / 40;          // 0..15
        int rg    = tid - split * 40;  // 0..39
        int rowb  = 4 * rg;            // local row base 0..156
        int g     = rg / 10;           // gate index (4-row groups don't cross gates)
        const float* WT = (split < 8) ? WiT : WhT;
        int cb = (split & 7) * 40;     // col base within the 320-wide matrix
        // global weight row = 280g + 40*rank + rowb
        const float* w0 = WT + (cb * 1280) + 280 * g + 40 * rank + rowb;
        const float (*a)[MB] = in + ((split < 8 ? 0 : 320) + cb);
        float acc[4][MB];
        #pragma unroll
        for (int i = 0; i < 4; ++i)
            #pragma unroll
            for (int m = 0; m < MB; ++m) acc[i][m] = 0.f;
        #pragma unroll 4
        for (int cc = 0; cc < 40; ++cc) {
            float4 w = *(const float4*)(w0 + cc * 1280);
            float4 xv = *(const float4*)&a[cc][0];
            float xm[MB] = {xv.x, xv.y, xv.z, xv.w};
            #pragma unroll
            for (int m = 0; m < MB; ++m) {
                acc[0][m] = fmaf(w.x, xm[m], acc[0][m]);
                acc[1][m] = fmaf(w.y, xm[m], acc[1][m]);
                acc[2][m] = fmaf(w.z, xm[m], acc[2][m]);
                acc[3][m] = fmaf(w.w, xm[m], acc[3][m]);
            }
        }
        #pragma unroll
        for (int i = 0; i < 4; ++i) {
            int lrow = rowb + i;
            #pragma unroll
            for (int m = 0; m < MB; ++m)
                scratch[(split * MB + m) * GROWS + lrow] = acc[i][m];
        }
    }
    __syncthreads();
    if (tid < MB * GROWS) {            // 640 outputs
        int m = tid / GROWS, r = tid - m * GROWS;
        float v = scratch[(0 * MB + m) * GROWS + r];
        #pragma unroll
        for (int s = 1; s < 16; ++s) v += scratch[(s * MB + m) * GROWS + r];
        int g = r / UNITS_PER, lu = r - g * UNITS_PER;
        gout[m][r] = v + bias[g * PRED + rank * UNITS_PER + lu];
    }
    // caller syncs before consuming gout
}

// ---------------- joint GEMV: 32 col-splits x 42 cols, float4 rows x 4 batches ----------------
// Local rows: 64 (rank slice of 512). Cols: 1344 = 32 splits x 42.
__device__ __forceinline__ void gemv_joint_T(
    const float* __restrict__ WT, const float* __restrict__ bias,
    const float (*zin)[MB],            // [1344][MB]
    float (*hid)[JH],                  // [MB][512], assembled cluster-wide
    float* scratch, int rank, int tid)
{
    if (tid < 512) {
        int split = tid >> 4;          // 0..31
        int rg    = tid & 15;
        int rowb  = 4 * rg;            // 0..60
        const float* w0 = WT + (split * 42) * 512 + rank * JROWS_PER + rowb;
        const float (*a)[MB] = zin + split * 42;
        float acc[4][MB];
        #pragma unroll
        for (int i = 0; i < 4; ++i)
            #pragma unroll
            for (int m = 0; m < MB; ++m) acc[i][m] = 0.f;
        #pragma unroll 6
        for (int cc = 0; cc < 42; ++cc) {
            float4 w = *(const float4*)(w0 + cc * 512);
            float4 xv = *(const float4*)&a[cc][0];
            float xm[MB] = {xv.x, xv.y, xv.z, xv.w};
            #pragma unroll
            for (int m = 0; m < MB; ++m) {
                acc[0][m] = fmaf(w.x, xm[m], acc[0][m]);
                acc[1][m] = fmaf(w.y, xm[m], acc[1][m]);
                acc[2][m] = fmaf(w.z, xm[m], acc[2][m]);
                acc[3][m] = fmaf(w.w, xm[m], acc[3][m]);
            }
        }
        #pragma unroll
        for (int i = 0; i < 4; ++i) {
            int lrow = rowb + i;
            #pragma unroll
            for (int m = 0; m < MB; ++m)
                scratch[(split * MB + m) * JROWS_PER + lrow] = acc[i][m];
        }
    }
    __syncthreads();
    if (tid < MB * JROWS_PER) {        // 256 outputs
        int m = tid / JROWS_PER, lr = tid - m * JROWS_PER;
        float v = scratch[(0 * MB + m) * JROWS_PER + lr];
        #pragma unroll
        for (int s = 1; s < 32; ++s) v += scratch[(s * MB + m) * JROWS_PER + lr];
        v += bias[rank * JROWS_PER + lr];
        v = v > 0.f ? v : 0.f;
        uint32_t ad = s2u(&hid[m][rank * JROWS_PER + lr]);
        #pragma unroll
        for (int rk = 0; rk < CSIZE; ++rk) st_peer(ad, rk, v);
    }
    // caller cluster-syncs
}

__global__ __launch_bounds__(NTHREADS, 1) __cluster_dims__(CSIZE, 1, 1)
void rnnt_greedy_kernel(const float* __restrict__ x,
                        const int*   __restrict__ out_lens,
                        const float* __restrict__ emb,
                        const float* __restrict__ b0, const float* __restrict__ b1,
                        const float* __restrict__ bj1,
                        const float* __restrict__ Wj2, const float* __restrict__ bj2,
                        float* __restrict__ d_out, int write_lc)
{
    extern __shared__ __align__(16) char smem_raw[];
    Smem& S = *reinterpret_cast<Smem*>(smem_raw);

    const int tid  = threadIdx.x;
    const int lane = tid & 31;
    const int warp = tid >> 5;

    uint32_t rank;
    asm("mov.u32 %0, %%cluster_ctarank;" : "=r"(rank));
    const int cid   = blockIdx.x / CSIZE;
    const int bbase = cid * MB;

    __shared__ int s_last[MB], s_lc[MB], s_ti[MB], s_sa[MB], s_nb[MB], s_olen[MB];
    __shared__ int s_alldone;

    // ---- init ----
    for (int i = tid; i < MB * PRED; i += NTHREADS) {
        int m = i & (MB - 1), j = i >> 2;
        S.L0in[PRED + j][m] = 0.f;   // h0 = 0
        S.L1in[PRED + j][m] = 0.f;   // h1 = 0
    }
    for (int i = tid; i < MB * UNITS_PER; i += NTHREADS) {
        int m = i / UNITS_PER, j = i - m * UNITS_PER;
        S.c0s[m][j] = 0.f; S.c1s[m][j] = 0.f;
    }
    for (int i = tid; i < MB * NSTEPS; i += NTHREADS) {
        int m = i / NSTEPS, j = i - m * NSTEPS;
        S.lt[m][j] = -1;
    }
    if (tid == 0) {
        #pragma unroll
        for (int m = 0; m < MB; ++m) {
            s_last[m] = -1; s_lc[m] = 0; s_ti[m] = 0; s_sa[m] = 0; s_nb[m] = 0;
            s_olen[m] = out_lens[bbase + m];
        }
        s_alldone = 0;
    }
    __syncthreads();
    CLUSTER_SYNC();

    for (int step = 0; step < NSTEPS; ++step) {
        const bool active = (s_alldone == 0);   // uniform across cluster

        // ---- P0: encoder frame -> zj[0:1024][.], embedding -> L0in[0:320][.] ----
        if (active) {
            for (int i = tid; i < MB * ENC; i += NTHREADS) {
                int m = i & (MB - 1), col = i >> 2;
                int fi = s_ti[m]; if (fi > TLEN - 1) fi = TLEN - 1;
                S.zj[col][m] = x[((bbase + m) * TLEN + fi) * ENC + col];
            }
            for (int i = tid; i < MB * PRED; i += NTHREADS) {
                int m = i & (MB - 1), col = i >> 2;
                int lab = s_last[m];
                int labc = lab > (VOCAB - 2) ? (VOCAB - 2) : lab;
                S.L0in[col][m] = (lab >= 0) ? emb[labc * PRED + col] : 0.0f;
            }
        }
        __syncthreads();

        // ---- P1: layer-0 gates ----
        if (active)
            gemv_gates_T(d_WiT0, d_WhT0, b0, S.L0in, S.g, S.scratch, (int)rank, tid);
        __syncthreads();

        // ---- P2: LSTM0 nonlinearity; broadcast h0p slice to all 8 CTAs ----
        if (active && tid < MB * UNITS_PER) {
            int m = tid / UNITS_PER, lu = tid - m * UNITS_PER;
            float gi = S.g[m][lu],                 gf = S.g[m][UNITS_PER + lu];
            float gg = S.g[m][2 * UNITS_PER + lu], go = S.g[m][3 * UNITS_PER + lu];
            float c  = sigf(gf) * S.c0s[m][lu] + sigf(gi) * tanhf(gg);
            S.c0p[m][lu] = c;
            float h  = sigf(go) * tanhf(c);
            uint32_t a = s2u(&S.L1in[rank * UNITS_PER + lu][m]);
            #pragma unroll
            for (int rk = 0; rk < CSIZE; ++rk) st_peer(a, rk, h);
        }
        CLUSTER_SYNC();   // S1: full h0p in L1in[0:320][.] everywhere

        // ---- P3: layer-1 gates ----
        if (active)
            gemv_gates_T(d_WiT1, d_WhT1, b1, S.L1in, S.g, S.scratch, (int)rank, tid);
        __syncthreads();

        // ---- P4: LSTM1 nonlinearity; broadcast h1p slice ----
        if (active && tid < MB * UNITS_PER) {
            int m = tid / UNITS_PER, lu = tid - m * UNITS_PER;
            float gi = S.g[m][lu],                 gf = S.g[m][UNITS_PER + lu];
            float gg = S.g[m][2 * UNITS_PER + lu], go = S.g[m][3 * UNITS_PER + lu];
            float c  = sigf(gf) * S.c1s[m][lu] + sigf(gi) * tanhf(gg);
            S.c1p[m][lu] = c;
            float h  = sigf(go) * tanhf(c);
            uint32_t a = s2u(&S.zj[ENC + rank * UNITS_PER + lu][m]);
            #pragma unroll
            for (int rk = 0; rk < CSIZE; ++rk) st_peer(a, rk, h);
        }
        CLUSTER_SYNC();   // S2: full [f|h1p] in zj everywhere

        // ---- P5: joint hidden (broadcasts hid) ----
        if (active)
            gemv_joint_T(d_Wj1T, bj1, S.zj, S.hid, S.scratch, (int)rank, tid);
        CLUSTER_SYNC();   // S3: full hid everywhere

        // ---- P6: logits (replicated; warp per vocab row, 4 batches) ----
        if (active) {
            for (int v = warp; v < VOCAB; v += (NTHREADS / 32)) {
                const float* w = Wj2 + v * JH + 16 * lane;
                float4 wv[4];
                #pragma unroll
                for (int j = 0; j < 4; ++j) wv[j] = *(const float4*)(w + 4 * j);
                float acc[MB] = {0.f, 0.f, 0.f, 0.f};
                #pragma unroll
                for (int m = 0; m < MB; ++m) {
                    #pragma unroll
                    for (int j = 0; j < 4; ++j) {
                        float4 hv = *(const float4*)&S.hid[m][16 * lane + 4 * j];
                        acc[m] = fmaf(wv[j].x, hv.x, acc[m]); acc[m] = fmaf(wv[j].y, hv.y, acc[m]);
                        acc[m] = fmaf(wv[j].z, hv.z, acc[m]); acc[m] = fmaf(wv[j].w, hv.w, acc[m]);
                    }
                }
                #pragma unroll
                for (int o = 16; o > 0; o >>= 1) {
                    acc[0] += __shfl_down_sync(0xffffffffu, acc[0], o);
                    acc[1] += __shfl_down_sync(0xffffffffu, acc[1], o);
                    acc[2] += __shfl_down_sync(0xffffffffu, acc[2], o);
                    acc[3] += __shfl_down_sync(0xffffffffu, acc[3], o);
                }
                if (lane == 0) {
                    float bb = bj2[v];
                    #pragma unroll
                    for (int m = 0; m < MB; ++m) S.logit[m][v] = acc[m] + bb;
                }
            }
        }
        __syncthreads();

        // ---- P7: argmax + control (replicated; identical in every CTA) ----
        if (active && tid == 0) {
            int ndone = 0;
            #pragma unroll
            for (int m = 0; m < MB; ++m) {
                float best = S.logit[m][0]; int k = 0;
                #pragma unroll
                for (int v = 1; v < VOCAB; ++v) {
                    float lv = S.logit[m][v];
                    if (lv > best) { best = lv; k = v; }
                }
                int ti = s_ti[m], sa = s_sa[m], lc = s_lc[m];
                bool blk = (k == BLANK);
                if (blk) ti += 1;
                bool done = (ti >= s_olen[m]);
                if (blk) sa = 0;
                bool nb = !(done || blk);
                if (nb) {
                    lc += 1;
                    if (lc <= NSTEPS - 1) S.lt[m][lc] += (k + 1);  // JAX scatter: OOB dropped
                    sa += 1;
                }
                {
                    int pos = lc; if (pos > NSTEPS - 1) pos = NSTEPS - 1;
                    s_last[m] = S.lt[m][pos];                       // JAX gather: clamp
                }
                if (sa >= MAXSYM) { ti += 1; sa = 0; }
                s_ti[m] = ti; s_sa[m] = sa; s_lc[m] = lc; s_nb[m] = nb ? 1 : 0;
                if (ti >= s_olen[m]) ndone += 1;
            }
            if (ndone == MB) s_alldone = 1;   // outputs frozen from here on
        }
        __syncthreads();

        // ---- P8: conditional state commit ----
        if (active) {
            for (int i = tid; i < MB * PRED; i += NTHREADS) {
                int m = i & (MB - 1), u = i >> 2;
                if (s_nb[m]) {
                    S.L0in[PRED + u][m] = S.L1in[u][m];        // h0 <- h0p
                    S.L1in[PRED + u][m] = S.zj[ENC + u][m];    // h1 <- h1p
                }
            }
            if (tid < MB * UNITS_PER) {
                int m = tid / UNITS_PER, lu = tid - m * UNITS_PER;
                if (s_nb[m]) { S.c0s[m][lu] = S.c0p[m][lu]; S.c1s[m][lu] = S.c1p[m][lu]; }
            }
        }
        CLUSTER_SYNC();   // S4: protects h0p/h1p regions against next step's peer writes
    }

    // ---- output (rank 0): lt as float32, then lc ----
    if (rank == 0) {
        for (int m = 0; m < MB; ++m) {
            for (int i = tid; i < NSTEPS; i += NTHREADS)
                d_out[(bbase + m) * NSTEPS + i] = (float)S.lt[m][i];
        }
        if (tid == 0 && write_lc) {
            #pragma unroll
            for (int m = 0; m < MB; ++m)
                d_out[BATCH * NSTEPS + bbase + m] = (float)s_lc[m];
        }
    }
}

extern "C" void kernel_launch(void* const* d_in, const int* in_sizes, int n_in,
                              void* d_out, int out_size) {
    const float* x        = (const float*)d_in[0];
    const int*   out_lens = (const int*)  d_in[1];
    const float* emb      = (const float*)d_in[2];
    const float* Wi0      = (const float*)d_in[3];
    const float* Wh0      = (const float*)d_in[4];
    const float* b0       = (const float*)d_in[5];
    const float* Wi1      = (const float*)d_in[6];
    const float* Wh1      = (const float*)d_in[7];
    const float* b1       = (const float*)d_in[8];
    const float* Wj1      = (const float*)d_in[9];
    const float* bj1      = (const float*)d_in[10];
    const float* Wj2      = (const float*)d_in[11];
    const float* bj2      = (const float*)d_in[12];

    int write_lc = (out_size >= BATCH * NSTEPS + BATCH) ? 1 : 0;

    // Opt-in to >48KB dynamic smem (idempotent; not a memory allocation).
    static int attr_done = 0;
    if (!attr_done) {
        cudaFuncSetAttribute(rnnt_greedy_kernel,
                             cudaFuncAttributeMaxDynamicSharedMemorySize, SMEM_BYTES);
        attr_done = 1;
    }

    dim3 tb(32, 8);
    transpose_kernel<<<512, tb>>>(Wi0, 4 * PRED, PRED, 0);
    transpose_kernel<<<512, tb>>>(Wh0, 4 * PRED, PRED, 1);
    transpose_kernel<<<512, tb>>>(Wi1, 4 * PRED, PRED, 2);
    transpose_kernel<<<512, tb>>>(Wh1, 4 * PRED, PRED, 3);
    transpose_kernel<<<512, tb>>>(Wj1, JH, ZDIM, 4);

    rnnt_greedy_kernel<<<(BATCH / MB) * CSIZE, NTHREADS, SMEM_BYTES>>>(
        x, out_lens, emb, b0, b1, bj1, Wj2, bj2,
        (float*)d_out, write_lc);
}

// round 16
// speedup vs baseline: 1.2570x; 1.0906x over previous
#include <cuda_runtime.h>
#include <math.h>
#include <stdint.h>

#define ENC 1024
#define PRED 320
#define JH 512
#define VOCAB 29
#define BLANK 28
#define MAXSYM 6
#define BATCH 32
#define TLEN 48
#define NSTEPS 288
#define ZDIM 1344
#define CSIZE 8
#define MB 4
#define NTHREADS 640
#define UNITS_PER (PRED / CSIZE)   // 40
#define GROWS (4 * UNITS_PER)      // 160 local gate rows
#define JROWS_PER (JH / CSIZE)     // 64

// Transposed weight scratch (one-time fill per launch; ~9.3 MB)
__device__ float d_WiT0[PRED * 4 * PRED];   // [320 cols][1280 rows]
__device__ float d_WhT0[PRED * 4 * PRED];
__device__ float d_WiT1[PRED * 4 * PRED];
__device__ float d_WhT1[PRED * 4 * PRED];
__device__ float d_Wj1T[ZDIM * JH];         // [1344 cols][512 rows]

#define CLUSTER_SYNC() do { \
    asm volatile("barrier.cluster.arrive.aligned;" ::: "memory"); \
    asm volatile("barrier.cluster.wait.aligned;"   ::: "memory"); \
} while (0)

__device__ __forceinline__ float sigf(float v) { return 1.0f / (1.0f + expf(-v)); }

__device__ __forceinline__ void redsum4(float& a, float& b, float& c, float& d) {
    #pragma unroll
    for (int o = 16; o > 0; o >>= 1) {
        a += __shfl_down_sync(0xffffffffu, a, o);
        b += __shfl_down_sync(0xffffffffu, b, o);
        c += __shfl_down_sync(0xffffffffu, c, o);
        d += __shfl_down_sync(0xffffffffu, d, o);
    }
}

__device__ __forceinline__ uint32_t s2u(const void* p) {
    return (uint32_t)__cvta_generic_to_shared((void*)p);
}

__device__ __forceinline__ void st_peer(uint32_t addr, int rank, float v) {
    uint32_t pa;
    asm volatile("mapa.shared::cluster.u32 %0, %1, %2;" : "=r"(pa) : "r"(addr), "r"(rank));
    asm volatile("st.shared::cluster.f32 [%0], %1;" :: "r"(pa), "f"(v));
}

// ---------------- tiled transpose: out[c][r] = in[r][c]; R,C multiples of 32 ----------------
__global__ void transpose_kernel(const float* __restrict__ in, int R, int C, int which) {
    float* out = (which == 0) ? d_WiT0 : (which == 1) ? d_WhT0 :
                 (which == 2) ? d_WiT1 : (which == 3) ? d_WhT1 : d_Wj1T;
    __shared__ float tile[32][33];
    int tilesC = C >> 5, tilesR = R >> 5;
    int ntiles = tilesC * tilesR;
    for (int t = blockIdx.x; t < ntiles; t += gridDim.x) {
        int tc = t % tilesC, tr = t / tilesC;
        int c0 = tc << 5, r0 = tr << 5;
        __syncthreads();
        #pragma unroll
        for (int j = 0; j < 32; j += 8)
            tile[threadIdx.y + j][threadIdx.x] = in[(size_t)(r0 + threadIdx.y + j) * C + c0 + threadIdx.x];
        __syncthreads();
        #pragma unroll
        for (int j = 0; j < 32; j += 8)
            out[(size_t)(c0 + threadIdx.y + j) * R + r0 + threadIdx.x] = tile[threadIdx.x][threadIdx.y + j];
    }
}

// ---------------- dynamic shared-memory layout ----------------
// Activations interleaved [col][MB]; one LDS.128 (warp-broadcast) fetches all 4 batch values.
struct Smem {
    float L0in[2 * PRED][MB];     // cols [0:320]=e, [320:640]=h0(state)
    float L1in[2 * PRED][MB];     // cols [0:320]=h0p, [320:640]=h1(state)
    float zj[ZDIM][MB];           // cols [0:1024]=f, [1024:1344]=h1p
    float c0s[MB][UNITS_PER], c1s[MB][UNITS_PER];
    float c0p[MB][UNITS_PER], c1p[MB][UNITS_PER];
    float scratch[16 * MB * GROWS];   // gates: 16*4*160=10240; joint subset 32*4*64=8192
    float hidl[MB][JROWS_PER];        // LOCAL hid slice only (no broadcast)
    float logitp[CSIZE][MB][32];      // per-rank logit partials (replicated via push)
    float logit[MB][32];
    int   lt[MB][NSTEPS];
};
#define SMEM_BYTES ((int)sizeof(Smem))

// ---------------- gate GEMV compute: 16 col-splits x 40 cols, float4 rows x 4 batches ----------------
// Writes 16 partials per (m,row) into scratch. NO reduce here (fused into nonlin phase).
__device__ __forceinline__ void gates_compute(
    const float* __restrict__ WiT, const float* __restrict__ WhT,
    const float (*in)[MB],             // [640][MB]
    float* scratch, int rank, int tid)
{
    int split = tid / 40;          // 0..15
    int rg    = tid - split * 40;  // 0..39
    int rowb  = 4 * rg;            // local row base 0..156
    int g     = rg / 10;           // gate index (4-row groups don't cross gates)
    const float* WT = (split < 8) ? WiT : WhT;
    int cb = (split & 7) * 40;     // col base within the 320-wide matrix
    const float* w0 = WT + (cb * 1280) + 280 * g + 40 * rank + rowb;
    const float (*a)[MB] = in + ((split < 8 ? 0 : 320) + cb);
    float acc[4][MB];
    #pragma unroll
    for (int i = 0; i < 4; ++i)
        #pragma unroll
        for (int m = 0; m < MB; ++m) acc[i][m] = 0.f;
    #pragma unroll 4
    for (int cc = 0; cc < 40; ++cc) {
        float4 w = *(const float4*)(w0 + cc * 1280);
        float4 xv = *(const float4*)&a[cc][0];
        float xm[MB] = {xv.x, xv.y, xv.z, xv.w};
        #pragma unroll
        for (int m = 0; m < MB; ++m) {
            acc[0][m] = fmaf(w.x, xm[m], acc[0][m]);
            acc[1][m] = fmaf(w.y, xm[m], acc[1][m]);
            acc[2][m] = fmaf(w.z, xm[m], acc[2][m]);
            acc[3][m] = fmaf(w.w, xm[m], acc[3][m]);
        }
    }
    #pragma unroll
    for (int i = 0; i < 4; ++i) {
        int lrow = rowb + i;
        #pragma unroll
        for (int m = 0; m < MB; ++m)
            scratch[(split * MB + m) * GROWS + lrow] = acc[i][m];
    }
}

// ---------------- joint GEMV compute: 32 col-splits x 42 cols ----------------
__device__ __forceinline__ void joint_compute(
    const float* __restrict__ WT,
    const float (*zin)[MB],            // [1344][MB]
    float* scratch, int rank, int tid)
{
    if (tid < 512) {
        int split = tid >> 4;          // 0..31
        int rg    = tid & 15;
        int rowb  = 4 * rg;            // 0..60
        const float* w0 = WT + (split * 42) * 512 + rank * JROWS_PER + rowb;
        const float (*a)[MB] = zin + split * 42;
        float acc[4][MB];
        #pragma unroll
        for (int i = 0; i < 4; ++i)
            #pragma unroll
            for (int m = 0; m < MB; ++m) acc[i][m] = 0.f;
        #pragma unroll 6
        for (int cc = 0; cc < 42; ++cc) {
            float4 w = *(const float4*)(w0 + cc * 512);
            float4 xv = *(const float4*)&a[cc][0];
            float xm[MB] = {xv.x, xv.y, xv.z, xv.w};
            #pragma unroll
            for (int m = 0; m < MB; ++m) {
                acc[0][m] = fmaf(w.x, xm[m], acc[0][m]);
                acc[1][m] = fmaf(w.y, xm[m], acc[1][m]);
                acc[2][m] = fmaf(w.z, xm[m], acc[2][m]);
                acc[3][m] = fmaf(w.w, xm[m], acc[3][m]);
            }
        }
        #pragma unroll
        for (int i = 0; i < 4; ++i) {
            int lrow = rowb + i;
            #pragma unroll
            for (int m = 0; m < MB; ++m)
                scratch[(split * MB + m) * JROWS_PER + lrow] = acc[i][m];
        }
    }
}

__global__ __launch_bounds__(NTHREADS, 1) __cluster_dims__(CSIZE, 1, 1)
void rnnt_greedy_kernel(const float* __restrict__ x,
                        const int*   __restrict__ out_lens,
                        const float* __restrict__ emb,
                        const float* __restrict__ b0, const float* __restrict__ b1,
                        const float* __restrict__ bj1,
                        const float* __restrict__ Wj2, const float* __restrict__ bj2,
                        float* __restrict__ d_out, int write_lc)
{
    extern __shared__ __align__(16) char smem_raw[];
    Smem& S = *reinterpret_cast<Smem*>(smem_raw);

    const int tid  = threadIdx.x;
    const int lane = tid & 31;
    const int warp = tid >> 5;

    uint32_t rank;
    asm("mov.u32 %0, %%cluster_ctarank;" : "=r"(rank));
    const int cid   = blockIdx.x / CSIZE;
    const int bbase = cid * MB;

    __shared__ int s_last[MB], s_lc[MB], s_ti[MB], s_sa[MB], s_nb[MB], s_olen[MB];
    __shared__ int s_alldone;

    // ---- init state ----
    for (int i = tid; i < MB * PRED; i += NTHREADS) {
        int m = i & (MB - 1), j = i >> 2;
        S.L0in[PRED + j][m] = 0.f;   // h0 = 0
        S.L1in[PRED + j][m] = 0.f;   // h1 = 0
    }
    for (int i = tid; i < MB * UNITS_PER; i += NTHREADS) {
        int m = i / UNITS_PER, j = i - m * UNITS_PER;
        S.c0s[m][j] = 0.f; S.c1s[m][j] = 0.f;
    }
    for (int i = tid; i < MB * NSTEPS; i += NTHREADS) {
        int m = i / NSTEPS, j = i - m * NSTEPS;
        S.lt[m][j] = -1;
    }
    if (tid == 0) {
        #pragma unroll
        for (int m = 0; m < MB; ++m) {
            s_last[m] = -1; s_lc[m] = 0; s_ti[m] = 0; s_sa[m] = 0; s_nb[m] = 0;
            s_olen[m] = out_lens[bbase + m];
        }
        s_alldone = 0;
    }
    __syncthreads();

    // ---- initial P0: f = x[:,0,:], e = 0 (last = -1) ----
    for (int i = tid; i < MB * ENC; i += NTHREADS) {
        int m = i & (MB - 1), col = i >> 2;
        S.zj[col][m] = x[((bbase + m) * TLEN + 0) * ENC + col];
    }
    for (int i = tid; i < MB * PRED; i += NTHREADS) {
        int m = i & (MB - 1), col = i >> 2;
        S.L0in[col][m] = 0.0f;
    }
    __syncthreads();
    CLUSTER_SYNC();

    for (int step = 0; step < NSTEPS; ++step) {
        const bool active = (s_alldone == 0);   // uniform across cluster

        // ---- A: gates0 compute ----
        if (active)
            gates_compute(d_WiT0, d_WhT0, S.L0in, S.scratch, (int)rank, tid);
        __syncthreads();

        // ---- B: fused gate0 reduce + LSTM0 nonlin + h0p broadcast ----
        if (active && tid < MB * UNITS_PER) {
            int m = tid / UNITS_PER, lu = tid - m * UNITS_PER;
            float gv[4];
            #pragma unroll
            for (int g = 0; g < 4; ++g) {
                int r = g * UNITS_PER + lu;
                float v = S.scratch[(0 * MB + m) * GROWS + r];
                #pragma unroll
                for (int s = 1; s < 16; ++s) v += S.scratch[(s * MB + m) * GROWS + r];
                gv[g] = v + b0[g * PRED + rank * UNITS_PER + lu];
            }
            float c = sigf(gv[1]) * S.c0s[m][lu] + sigf(gv[0]) * tanhf(gv[2]);
            S.c0p[m][lu] = c;
            float h = sigf(gv[3]) * tanhf(c);
            uint32_t a = s2u(&S.L1in[rank * UNITS_PER + lu][m]);
            #pragma unroll
            for (int rk = 0; rk < CSIZE; ++rk) st_peer(a, rk, h);
        }
        CLUSTER_SYNC();   // S1: full h0p everywhere

        // ---- C: gates1 compute ----
        if (active)
            gates_compute(d_WiT1, d_WhT1, S.L1in, S.scratch, (int)rank, tid);
        __syncthreads();

        // ---- D: fused gate1 reduce + LSTM1 nonlin + h1p broadcast ----
        if (active && tid < MB * UNITS_PER) {
            int m = tid / UNITS_PER, lu = tid - m * UNITS_PER;
            float gv[4];
            #pragma unroll
            for (int g = 0; g < 4; ++g) {
                int r = g * UNITS_PER + lu;
                float v = S.scratch[(0 * MB + m) * GROWS + r];
                #pragma unroll
                for (int s = 1; s < 16; ++s) v += S.scratch[(s * MB + m) * GROWS + r];
                gv[g] = v + b1[g * PRED + rank * UNITS_PER + lu];
            }
            float c = sigf(gv[1]) * S.c1s[m][lu] + sigf(gv[0]) * tanhf(gv[2]);
            S.c1p[m][lu] = c;
            float h = sigf(gv[3]) * tanhf(c);
            uint32_t a = s2u(&S.zj[ENC + rank * UNITS_PER + lu][m]);
            #pragma unroll
            for (int rk = 0; rk < CSIZE; ++rk) st_peer(a, rk, h);
        }
        CLUSTER_SYNC();   // S2: full [f|h1p] in zj everywhere

        // ---- E: joint compute ----
        if (active)
            joint_compute(d_Wj1T, S.zj, S.scratch, (int)rank, tid);
        __syncthreads();

        // ---- F: joint reduce -> LOCAL hid slice (+bias+relu) ----
        if (active && tid < MB * JROWS_PER) {
            int m = tid >> 6, lr = tid & 63;
            float v = S.scratch[(0 * MB + m) * JROWS_PER + lr];
            #pragma unroll
            for (int s = 1; s < 32; ++s) v += S.scratch[(s * MB + m) * JROWS_PER + lr];
            v += bj1[rank * JROWS_PER + lr];
            S.hidl[m][lr] = v > 0.f ? v : 0.f;
        }
        __syncthreads();

        // ---- G: logit partials from local hid slice; push to all peers ----
        if (active) {
            for (int v = warp; v < VOCAB; v += (NTHREADS / 32)) {
                float wA = Wj2[v * JH + rank * JROWS_PER + lane];
                float wB = Wj2[v * JH + rank * JROWS_PER + lane + 32];
                float a0 = fmaf(wB, S.hidl[0][lane + 32], wA * S.hidl[0][lane]);
                float a1 = fmaf(wB, S.hidl[1][lane + 32], wA * S.hidl[1][lane]);
                float a2 = fmaf(wB, S.hidl[2][lane + 32], wA * S.hidl[2][lane]);
                float a3 = fmaf(wB, S.hidl[3][lane + 32], wA * S.hidl[3][lane]);
                redsum4(a0, a1, a2, a3);
                float p0 = __shfl_sync(0xffffffffu, a0, 0);
                float p1 = __shfl_sync(0xffffffffu, a1, 0);
                float p2 = __shfl_sync(0xffffffffu, a2, 0);
                float p3 = __shfl_sync(0xffffffffu, a3, 0);
                if (lane < MB) {
                    float pv = (lane == 0) ? p0 : (lane == 1) ? p1 : (lane == 2) ? p2 : p3;
                    uint32_t ad = s2u(&S.logitp[rank][lane][v]);
                    #pragma unroll
                    for (int rk = 0; rk < CSIZE; ++rk) st_peer(ad, rk, pv);
                }
            }
        }
        CLUSTER_SYNC();   // S3: all rank partials everywhere

        // ---- H: final logits = sum of 8 rank partials + bias ----
        if (active && tid < MB * 32) {
            int m = tid >> 5, v = tid & 31;
            if (v < VOCAB) {
                float s = S.logitp[0][m][v];
                #pragma unroll
                for (int rk = 1; rk < CSIZE; ++rk) s += S.logitp[rk][m][v];
                S.logit[m][v] = s + bj2[v];
            }
        }
        __syncthreads();

        // ---- I: argmax + control (replicated; identical in every CTA) ----
        if (active && tid == 0) {
            int ndone = 0;
            #pragma unroll
            for (int m = 0; m < MB; ++m) {
                float best = S.logit[m][0]; int k = 0;
                #pragma unroll
                for (int v = 1; v < VOCAB; ++v) {
                    float lv = S.logit[m][v];
                    if (lv > best) { best = lv; k = v; }
                }
                int ti = s_ti[m], sa = s_sa[m], lc = s_lc[m];
                bool blk = (k == BLANK);
                if (blk) ti += 1;
                bool done = (ti >= s_olen[m]);
                if (blk) sa = 0;
                bool nb = !(done || blk);
                if (nb) {
                    lc += 1;
                    if (lc <= NSTEPS - 1) S.lt[m][lc] += (k + 1);  // JAX scatter: OOB dropped
                    sa += 1;
                }
                {
                    int pos = lc; if (pos > NSTEPS - 1) pos = NSTEPS - 1;
                    s_last[m] = S.lt[m][pos];                       // JAX gather: clamp
                }
                if (sa >= MAXSYM) { ti += 1; sa = 0; }
                s_ti[m] = ti; s_sa[m] = sa; s_lc[m] = lc; s_nb[m] = nb ? 1 : 0;
                if (ti >= s_olen[m]) ndone += 1;
            }
            if (ndone == MB) s_alldone = 1;   // outputs frozen from here on
        }
        __syncthreads();

        // ---- J: state commit + NEXT-step f/e loads (fused P8+P0) ----
        if (active) {
            for (int i = tid; i < MB * PRED; i += NTHREADS) {
                int m = i & (MB - 1), u = i >> 2;
                if (s_nb[m]) {
                    S.L0in[PRED + u][m] = S.L1in[u][m];        // h0 <- h0p
                    S.L1in[PRED + u][m] = S.zj[ENC + u][m];    // h1 <- h1p
                }
            }
            if (tid < MB * UNITS_PER) {
                int m = tid / UNITS_PER, lu = tid - m * UNITS_PER;
                if (s_nb[m]) { S.c0s[m][lu] = S.c0p[m][lu]; S.c1s[m][lu] = S.c1p[m][lu]; }
            }
            // next-step encoder frame + embedding (ti/last just updated in I)
            for (int i = tid; i < MB * ENC; i += NTHREADS) {
                int m = i & (MB - 1), col = i >> 2;
                int fi = s_ti[m]; if (fi > TLEN - 1) fi = TLEN - 1;
                S.zj[col][m] = x[((bbase + m) * TLEN + fi) * ENC + col];
            }
            for (int i = tid; i < MB * PRED; i += NTHREADS) {
                int m = i & (MB - 1), col = i >> 2;
                int lab = s_last[m];
                int labc = lab > (VOCAB - 2) ? (VOCAB - 2) : lab;
                S.L0in[col][m] = (lab >= 0) ? emb[labc * PRED + col] : 0.0f;
            }
        }
        CLUSTER_SYNC();   // S4: protects h0p/h1p/logitp regions for next step
    }

    // ---- output (rank 0): lt as float32, then lc ----
    if (rank == 0) {
        for (int m = 0; m < MB; ++m) {
            for (int i = tid; i < NSTEPS; i += NTHREADS)
                d_out[(bbase + m) * NSTEPS + i] = (float)S.lt[m][i];
        }
        if (tid == 0 && write_lc) {
            #pragma unroll
            for (int m = 0; m < MB; ++m)
                d_out[BATCH * NSTEPS + bbase + m] = (float)s_lc[m];
        }
    }
}

extern "C" void kernel_launch(void* const* d_in, const int* in_sizes, int n_in,
                              void* d_out, int out_size) {
    const float* x        = (const float*)d_in[0];
    const int*   out_lens = (const int*)  d_in[1];
    const float* emb      = (const float*)d_in[2];
    const float* Wi0      = (const float*)d_in[3];
    const float* Wh0      = (const float*)d_in[4];
    const float* b0       = (const float*)d_in[5];
    const float* Wi1      = (const float*)d_in[6];
    const float* Wh1      = (const float*)d_in[7];
    const float* b1       = (const float*)d_in[8];
    const float* Wj1      = (const float*)d_in[9];
    const float* bj1      = (const float*)d_in[10];
    const float* Wj2      = (const float*)d_in[11];
    const float* bj2      = (const float*)d_in[12];

    int write_lc = (out_size >= BATCH * NSTEPS + BATCH) ? 1 : 0;

    // Opt-in to >48KB dynamic smem (idempotent; not a memory allocation).
    static int attr_done = 0;
    if (!attr_done) {
        cudaFuncSetAttribute(rnnt_greedy_kernel,
                             cudaFuncAttributeMaxDynamicSharedMemorySize, SMEM_BYTES);
        attr_done = 1;
    }

    dim3 tb(32, 8);
    transpose_kernel<<<512, tb>>>(Wi0, 4 * PRED, PRED, 0);
    transpose_kernel<<<512, tb>>>(Wh0, 4 * PRED, PRED, 1);
    transpose_kernel<<<512, tb>>>(Wi1, 4 * PRED, PRED, 2);
    transpose_kernel<<<512, tb>>>(Wh1, 4 * PRED, PRED, 3);
    transpose_kernel<<<512, tb>>>(Wj1, JH, ZDIM, 4);

    rnnt_greedy_kernel<<<(BATCH / MB) * CSIZE, NTHREADS, SMEM_BYTES>>>(
        x, out_lens, emb, b0, b1, bj1, Wj2, bj2,
        (float*)d_out, write_lc);
}